// round 2
// baseline (speedup 1.0000x reference)
#include <cuda_runtime.h>

// TypeConditionalLinear: out[n] = input[n] @ weight[i_type[n]].T + bias[i_type[n]]
// N=16384 tokens, IN=512, OUT=512, T=16 types. fp32 in/out.
//
// Round 2: fix the i_type dtype trap. The reference declares int64, but JAX
// without x64 silently produces int32. Detect the layout on-device (OR of all
// odd int32 words == 0 <=> int64) and branch in the bucketing kernels.
// Phase 2 unchanged: fp32 tiled gather-GEMM (128x128x16, 8x8 micro-tiles).

#define N_TOK   16384
#define IN_F    512
#define OUT_F   512
#define N_TYPES 16

#define BM 128
#define BN 128
#define BK 16
#define MAX_TILES (N_TOK / BM + N_TYPES)   // 144 worst case

// ---------------- scratch (allocation-free: __device__ globals) ----------------
__device__ int g_counts[N_TYPES];
__device__ int g_fill[N_TYPES];
__device__ int g_offsets[N_TYPES + 1];
__device__ int g_perm[N_TOK];           // token ids bucketed by type
__device__ int g_tile_type[MAX_TILES];
__device__ int g_tile_start[MAX_TILES];
__device__ int g_tile_rows[MAX_TILES];
__device__ int g_num_tiles;
__device__ int g_odd_or;                // !=0  =>  i_type is int32

// ---------------- dtype handling ----------------
__device__ __forceinline__ int load_type(const void* it, int n) {
    // g_odd_or == 0  => all odd 32-bit words are zero => int64 layout
    if (g_odd_or == 0)
        return ((int)((const long long*)it)[n]) & (N_TYPES - 1);
    return ((const int*)it)[n] & (N_TYPES - 1);
}

__global__ void tcl_zero_kernel() {
    int t = threadIdx.x;
    if (t < N_TYPES) { g_counts[t] = 0; g_fill[t] = 0; }
    if (t == 0) g_odd_or = 0;
}

// OR all odd int32 words of the first N_TOK int32 slots (safe for both layouts:
// reads 64 KB, and the buffer is >= 64 KB in either dtype).
__global__ void tcl_detect_kernel(const int* __restrict__ it32) {
    int i = blockIdx.x * blockDim.x + threadIdx.x;   // 0 .. N_TOK/2-1
    int v = it32[2 * i + 1];
    // warp-reduce then one atomic per warp
    #pragma unroll
    for (int s = 16; s > 0; s >>= 1) v |= __shfl_xor_sync(0xffffffffu, v, s);
    if ((threadIdx.x & 31) == 0 && v) atomicOr(&g_odd_or, v);
}

// ---------------- phase 1: bucketing ----------------
__global__ void tcl_hist_kernel(const void* __restrict__ i_type) {
    int n = blockIdx.x * blockDim.x + threadIdx.x;
    if (n < N_TOK) atomicAdd(&g_counts[load_type(i_type, n)], 1);
}

__global__ void tcl_prefix_kernel() {
    int off = 0;
    for (int t = 0; t < N_TYPES; t++) { g_offsets[t] = off; off += g_counts[t]; }
    g_offsets[N_TYPES] = off;
    int nt = 0;
    for (int t = 0; t < N_TYPES; t++) {
        int c = g_counts[t];
        for (int s = 0; s < c; s += BM) {
            g_tile_type[nt]  = t;
            g_tile_start[nt] = g_offsets[t] + s;
            g_tile_rows[nt]  = (c - s < BM) ? (c - s) : BM;
            nt++;
        }
    }
    g_num_tiles = nt;
}

__global__ void tcl_scatter_kernel(const void* __restrict__ i_type) {
    int n = blockIdx.x * blockDim.x + threadIdx.x;
    if (n < N_TOK) {
        int t = load_type(i_type, n);
        int pos = g_offsets[t] + atomicAdd(&g_fill[t], 1);
        if (pos >= 0 && pos < N_TOK) g_perm[pos] = n;
    }
}

// ---------------- phase 2: gather-GEMM ----------------
__global__ __launch_bounds__(256, 2)
void tcl_gemm_kernel(const float* __restrict__ input,
                     const float* __restrict__ weight,
                     const float* __restrict__ bias,
                     float* __restrict__ out)
{
    const int mt = blockIdx.y;
    if (mt >= g_num_tiles) return;

    const int nStart   = blockIdx.x * BN;
    const int type     = g_tile_type[mt];
    const int rowStart = g_tile_start[mt];
    const int rows     = g_tile_rows[mt];

    __shared__ float As[BK][BM];   // [k][m]
    __shared__ float Bs[BK][BN];   // [k][n]
    __shared__ int   sToken[BM];

    const int tid = threadIdx.x;

    if (tid < BM)
        sToken[tid] = (tid < rows) ? g_perm[rowStart + tid] : -1;
    __syncthreads();

    const float* __restrict__ W = weight + (size_t)type * OUT_F * IN_F;

    float acc[8][8];
    #pragma unroll
    for (int i = 0; i < 8; i++)
        #pragma unroll
        for (int j = 0; j < 8; j++)
            acc[i][j] = 0.0f;

    const int tcol = (tid & 15) * 8;   // N offset of micro-tile
    const int trow = (tid >> 4) * 8;   // M offset of micro-tile

    for (int k0 = 0; k0 < IN_F; k0 += BK) {
        #pragma unroll
        for (int l = 0; l < 2; l++) {
            int c  = tid * 2 + l;        // 0..511
            int m  = c >> 2;             // 0..127
            int kq = (c & 3) * 4;        // 0,4,8,12
            int tok = sToken[m];
            float4 v = make_float4(0.f, 0.f, 0.f, 0.f);
            if (tok >= 0)
                v = *reinterpret_cast<const float4*>(input + (size_t)tok * IN_F + k0 + kq);
            As[kq + 0][m] = v.x; As[kq + 1][m] = v.y;
            As[kq + 2][m] = v.z; As[kq + 3][m] = v.w;
        }
        #pragma unroll
        for (int l = 0; l < 2; l++) {
            int c  = tid * 2 + l;
            int n  = c >> 2;
            int kq = (c & 3) * 4;
            float4 v = *reinterpret_cast<const float4*>(
                W + (size_t)(nStart + n) * IN_F + k0 + kq);
            Bs[kq + 0][n] = v.x; Bs[kq + 1][n] = v.y;
            Bs[kq + 2][n] = v.z; Bs[kq + 3][n] = v.w;
        }
        __syncthreads();

        #pragma unroll
        for (int k = 0; k < BK; k++) {
            float a[8], b[8];
            *reinterpret_cast<float4*>(&a[0]) = *reinterpret_cast<const float4*>(&As[k][trow]);
            *reinterpret_cast<float4*>(&a[4]) = *reinterpret_cast<const float4*>(&As[k][trow + 4]);
            *reinterpret_cast<float4*>(&b[0]) = *reinterpret_cast<const float4*>(&Bs[k][tcol]);
            *reinterpret_cast<float4*>(&b[4]) = *reinterpret_cast<const float4*>(&Bs[k][tcol + 4]);
            #pragma unroll
            for (int i = 0; i < 8; i++)
                #pragma unroll
                for (int j = 0; j < 8; j++)
                    acc[i][j] += a[i] * b[j];
        }
        __syncthreads();
    }

    float bsv[8];
    *reinterpret_cast<float4*>(&bsv[0]) =
        *reinterpret_cast<const float4*>(bias + type * OUT_F + nStart + tcol);
    *reinterpret_cast<float4*>(&bsv[4]) =
        *reinterpret_cast<const float4*>(bias + type * OUT_F + nStart + tcol + 4);

    #pragma unroll
    for (int i = 0; i < 8; i++) {
        int m = trow + i;
        int tok = sToken[m];
        if (tok >= 0) {
            float* o = out + (size_t)tok * OUT_F + nStart + tcol;
            float4 o0 = make_float4(acc[i][0] + bsv[0], acc[i][1] + bsv[1],
                                    acc[i][2] + bsv[2], acc[i][3] + bsv[3]);
            float4 o1 = make_float4(acc[i][4] + bsv[4], acc[i][5] + bsv[5],
                                    acc[i][6] + bsv[6], acc[i][7] + bsv[7]);
            *reinterpret_cast<float4*>(o)     = o0;
            *reinterpret_cast<float4*>(o + 4) = o1;
        }
    }
}

// ---------------- launcher ----------------
extern "C" void kernel_launch(void* const* d_in, const int* in_sizes, int n_in,
                              void* d_out, int out_size)
{
    const float* input  = (const float*)d_in[0];
    const void*  i_type = d_in[1];
    const float* weight = (const float*)d_in[2];
    const float* bias   = (const float*)d_in[3];
    float*       out    = (float*)d_out;

    tcl_zero_kernel<<<1, 32>>>();
    tcl_detect_kernel<<<N_TOK / 2 / 256, 256>>>((const int*)i_type);
    tcl_hist_kernel<<<N_TOK / 256, 256>>>(i_type);
    tcl_prefix_kernel<<<1, 1>>>();
    tcl_scatter_kernel<<<N_TOK / 256, 256>>>(i_type);
    tcl_gemm_kernel<<<dim3(OUT_F / BN, MAX_TILES), 256>>>(input, weight, bias, out);
}

// round 4
// speedup vs baseline: 2.2305x; 2.2305x over previous
#include <cuda_runtime.h>
#include <cuda_bf16.h>
#include <cstdint>

// TypeConditionalLinear on sm_100 (non-'a' target: no tcgen05/TMEM).
// out[n] = input[n] @ weight[i_type[n]].T + bias[i_type[n]]
// N=16384, IN=OUT=512, T=16. fp32 in/out.
//
// Phase 1: bucket tokens by type into g_perm + per-type 128-row tile table.
// Phase 2: gather-GEMM via mma.sync.m16n8k16 bf16 with 3-product split
//          (hi*hi + lo*hi + hi*lo) for fp32-grade accuracy at bf16 speed.
//          CTA 128x128, 16 warps of 32x32, BK=32 double-buffered SMEM of
//          pre-split bf16 hi/lo tiles (80B row stride -> conflict-free ldmatrix).

#define N_TOK   16384
#define IN_F    512
#define OUT_F   512
#define N_TYPES 16

#define BM 128
#define BN 128
#define BK 32
#define N_SLABS (IN_F / BK)               // 16
#define MAX_TILES (N_TOK / BM + N_TYPES)  // 144
#define NTHREADS 512

#define ROW_B   80                        // bytes per smem row (32 bf16 + pad, 16B-mult)
#define TILE_B  (128 * ROW_B)             // 10240
#define A_HI    0
#define A_LO    TILE_B
#define B_HI    (2 * TILE_B)
#define B_LO    (3 * TILE_B)
#define STAGE_B (4 * TILE_B)              // 40960
#define SM_TOKEN 0
#define SM_BIAS  512
#define SM_STAGE 1024
#define SMEM_TOTAL (SM_STAGE + 2 * STAGE_B)   // 82944

// ---------------- scratch ----------------
__device__ int g_counts[N_TYPES];
__device__ int g_fill[N_TYPES];
__device__ int g_offsets[N_TYPES + 1];
__device__ int g_perm[N_TOK];
__device__ int g_tile_type[MAX_TILES];
__device__ int g_tile_start[MAX_TILES];
__device__ int g_tile_rows[MAX_TILES];
__device__ int g_num_tiles;
__device__ int g_odd_or;     // !=0 => i_type is int32

__device__ __forceinline__ int load_type(const void* it, int n) {
    if (g_odd_or == 0) return ((int)((const long long*)it)[n]) & (N_TYPES - 1);
    return ((const int*)it)[n] & (N_TYPES - 1);
}

// ---------------- phase 1 ----------------
__global__ void tcl_zero_kernel() {
    int t = threadIdx.x;
    if (t < N_TYPES) { g_counts[t] = 0; g_fill[t] = 0; }
    if (t == 0) g_odd_or = 0;
}

__global__ void tcl_detect_kernel(const int* __restrict__ it32) {
    int i = blockIdx.x * blockDim.x + threadIdx.x;
    int v = it32[2 * i + 1];
    #pragma unroll
    for (int s = 16; s > 0; s >>= 1) v |= __shfl_xor_sync(0xffffffffu, v, s);
    if ((threadIdx.x & 31) == 0 && v) atomicOr(&g_odd_or, v);
}

__global__ void tcl_hist_kernel(const void* __restrict__ i_type) {
    __shared__ int h[N_TYPES];
    if (threadIdx.x < N_TYPES) h[threadIdx.x] = 0;
    __syncthreads();
    int n = blockIdx.x * blockDim.x + threadIdx.x;
    if (n < N_TOK) atomicAdd(&h[load_type(i_type, n)], 1);
    __syncthreads();
    if (threadIdx.x < N_TYPES && h[threadIdx.x]) atomicAdd(&g_counts[threadIdx.x], h[threadIdx.x]);
}

__global__ void tcl_prefix_kernel() {   // 1 warp
    int t = threadIdx.x;
    int c = (t < N_TYPES) ? g_counts[t] : 0;
    int x = c;
    #pragma unroll
    for (int s = 1; s < 32; s <<= 1) {
        int y = __shfl_up_sync(0xffffffffu, x, s);
        if (t >= s) x += y;
    }
    int excl = x - c;
    if (t < N_TYPES) g_offsets[t] = excl;
    if (t == N_TYPES - 1) g_offsets[N_TYPES] = x;
    int nt = (t < N_TYPES) ? (c + BM - 1) / BM : 0;
    int y2 = nt;
    #pragma unroll
    for (int s = 1; s < 32; s <<= 1) {
        int y = __shfl_up_sync(0xffffffffu, y2, s);
        if (t >= s) y2 += y;
    }
    int tbase = y2 - nt;
    if (t == N_TYPES - 1) g_num_tiles = y2;
    if (t < N_TYPES) {
        for (int i = 0; i < nt; i++) {
            int idx = tbase + i;
            g_tile_type[idx]  = t;
            g_tile_start[idx] = excl + i * BM;
            g_tile_rows[idx]  = (c - i * BM < BM) ? (c - i * BM) : BM;
        }
    }
}

__global__ void tcl_scatter_kernel(const void* __restrict__ i_type) {
    int n = blockIdx.x * blockDim.x + threadIdx.x;
    if (n < N_TOK) {
        int t = load_type(i_type, n);
        int pos = g_offsets[t] + atomicAdd(&g_fill[t], 1);
        if (pos >= 0 && pos < N_TOK) g_perm[pos] = n;
    }
}

// ---------------- mma helpers ----------------
__device__ __forceinline__ uint32_t smem_u32(const void* p) {
    uint32_t a;
    asm("{ .reg .u64 t; cvta.to.shared.u64 t, %1; cvt.u32.u64 %0, t; }" : "=r"(a) : "l"(p));
    return a;
}

__device__ __forceinline__ void ldsm_x4(uint32_t* r, uint32_t addr) {
    asm volatile("ldmatrix.sync.aligned.m8n8.x4.shared.b16 {%0,%1,%2,%3}, [%4];"
                 : "=r"(r[0]), "=r"(r[1]), "=r"(r[2]), "=r"(r[3]) : "r"(addr));
}

__device__ __forceinline__ void mma_bf16(float* c, const uint32_t* a, const uint32_t* b) {
    asm volatile("mma.sync.aligned.m16n8k16.row.col.f32.bf16.bf16.f32 "
                 "{%0,%1,%2,%3}, {%4,%5,%6,%7}, {%8,%9}, {%0,%1,%2,%3};"
                 : "+f"(c[0]), "+f"(c[1]), "+f"(c[2]), "+f"(c[3])
                 : "r"(a[0]), "r"(a[1]), "r"(a[2]), "r"(a[3]), "r"(b[0]), "r"(b[1]));
}

__device__ __forceinline__ uint32_t pack2(__nv_bfloat16 a, __nv_bfloat16 b) {
    __nv_bfloat162 t; t.x = a; t.y = b;
    return *reinterpret_cast<uint32_t*>(&t);
}

__device__ __forceinline__ void split2(float x, float y, uint32_t& hi, uint32_t& lo) {
    __nv_bfloat16 hx = __float2bfloat16_rn(x);
    __nv_bfloat16 hy = __float2bfloat16_rn(y);
    float lx = x - __bfloat162float(hx);
    float ly = y - __bfloat162float(hy);
    hi = pack2(hx, hy);
    lo = pack2(__float2bfloat16_rn(lx), __float2bfloat16_rn(ly));
}

// ---------------- phase 2: gather-GEMM ----------------
__global__ __launch_bounds__(NTHREADS, 1)
void tcl_gemm_kernel(const float* __restrict__ input,
                     const float* __restrict__ weight,
                     const float* __restrict__ bias,
                     float* __restrict__ out)
{
    const int mt = blockIdx.y;
    if (mt >= g_num_tiles) return;

    extern __shared__ char smem[];
    const uint32_t sb = smem_u32(smem);
    const int tid  = threadIdx.x;
    const int wid  = tid >> 5;
    const int lane = tid & 31;

    const int nStart   = blockIdx.x * BN;
    const int type     = g_tile_type[mt];
    const int rowStart = g_tile_start[mt];
    const int rows     = g_tile_rows[mt];

    int*   sTok  = (int*)(smem + SM_TOKEN);
    float* sBias = (float*)(smem + SM_BIAS);

    if (tid < BM) sTok[tid] = (tid < rows) ? g_perm[rowStart + tid] : -1;
    if (tid >= 128 && tid < 256) sBias[tid - 128] = bias[type * OUT_F + nStart + tid - 128];
    __syncthreads();

    const float* __restrict__ Wt = weight + (size_t)type * OUT_F * IN_F;

    // producer indexing: 2 chunks of A and 2 of B per thread per slab
    const int pm  = tid >> 3;          // 0..63 (row base, +64 for second chunk)
    const int pkq = tid & 7;           // float4 index within 32-float row

    // warp tile: 4x4 warps of 32(m) x 32(n)
    const int wm0 = (wid & 3) * 32;
    const int wn0 = (wid >> 2) * 32;

    // ldmatrix per-lane offsets
    const int tile_id = lane >> 3;
    const int tw      = lane & 7;
    const int aoff = (wm0 + tw + (tile_id & 1) * 8) * ROW_B + ((tile_id >> 1) * 8) * 2;
    const int boff = (wn0 + tw + (tile_id >> 1) * 8) * ROW_B + ((tile_id & 1) * 8) * 2;

    float acc[2][4][4];
    #pragma unroll
    for (int mi = 0; mi < 2; mi++)
        #pragma unroll
        for (int nj = 0; nj < 4; nj++)
            #pragma unroll
            for (int e = 0; e < 4; e++) acc[mi][nj][e] = 0.f;

    float4 va[2], vb[2];

    auto ldg_slab = [&](int slab) {
        const int k0 = slab * BK;
        #pragma unroll
        for (int l = 0; l < 2; l++) {
            int m = pm + l * 64;
            int tok = sTok[m];
            va[l] = make_float4(0.f, 0.f, 0.f, 0.f);
            if (tok >= 0)
                va[l] = *reinterpret_cast<const float4*>(input + (size_t)tok * IN_F + k0 + pkq * 4);
            vb[l] = *reinterpret_cast<const float4*>(Wt + (size_t)(nStart + m) * IN_F + k0 + pkq * 4);
        }
    };

    auto sts_slab = [&](int stg) {
        char* st = smem + SM_STAGE + stg * STAGE_B;
        #pragma unroll
        for (int l = 0; l < 2; l++) {
            int m = pm + l * 64;
            int off = m * ROW_B + pkq * 8;
            uint32_t h0, l0, h1, l1;
            split2(va[l].x, va[l].y, h0, l0);
            split2(va[l].z, va[l].w, h1, l1);
            *reinterpret_cast<uint2*>(st + A_HI + off) = make_uint2(h0, h1);
            *reinterpret_cast<uint2*>(st + A_LO + off) = make_uint2(l0, l1);
            split2(vb[l].x, vb[l].y, h0, l0);
            split2(vb[l].z, vb[l].w, h1, l1);
            *reinterpret_cast<uint2*>(st + B_HI + off) = make_uint2(h0, h1);
            *reinterpret_cast<uint2*>(st + B_LO + off) = make_uint2(l0, l1);
        }
    };

    auto compute = [&](int stg) {
        const uint32_t st = sb + SM_STAGE + stg * STAGE_B;
        #pragma unroll
        for (int kk = 0; kk < BK; kk += 16) {
            uint32_t aH[2][4], aL[2][4], bH[4][2], bL[4][2], r[4];
            #pragma unroll
            for (int mi = 0; mi < 2; mi++) {
                ldsm_x4(aH[mi], st + A_HI + aoff + mi * 16 * ROW_B + kk * 2);
                ldsm_x4(aL[mi], st + A_LO + aoff + mi * 16 * ROW_B + kk * 2);
            }
            #pragma unroll
            for (int g = 0; g < 2; g++) {
                ldsm_x4(r, st + B_HI + boff + g * 16 * ROW_B + kk * 2);
                bH[g * 2][0] = r[0]; bH[g * 2][1] = r[1];
                bH[g * 2 + 1][0] = r[2]; bH[g * 2 + 1][1] = r[3];
                ldsm_x4(r, st + B_LO + boff + g * 16 * ROW_B + kk * 2);
                bL[g * 2][0] = r[0]; bL[g * 2][1] = r[1];
                bL[g * 2 + 1][0] = r[2]; bL[g * 2 + 1][1] = r[3];
            }
            #pragma unroll
            for (int mi = 0; mi < 2; mi++)
                #pragma unroll
                for (int nj = 0; nj < 4; nj++) {
                    mma_bf16(acc[mi][nj], aH[mi], bH[nj]);
                    mma_bf16(acc[mi][nj], aL[mi], bH[nj]);
                    mma_bf16(acc[mi][nj], aH[mi], bL[nj]);
                }
        }
    };

    // ---------------- pipelined mainloop ----------------
    ldg_slab(0);
    sts_slab(0);
    __syncthreads();
    for (int s = 0; s < N_SLABS; s++) {
        if (s + 1 < N_SLABS) ldg_slab(s + 1);
        compute(s & 1);
        if (s + 1 < N_SLABS) sts_slab((s + 1) & 1);
        __syncthreads();
    }

    // ---------------- epilogue ----------------
    #pragma unroll
    for (int mi = 0; mi < 2; mi++) {
        int r0 = wm0 + mi * 16 + (lane >> 2);
        int r1 = r0 + 8;
        int tok0 = sTok[r0];
        int tok1 = sTok[r1];
        #pragma unroll
        for (int nj = 0; nj < 4; nj++) {
            int col = wn0 + nj * 8 + (lane & 3) * 2;
            float b0 = sBias[col], b1 = sBias[col + 1];
            if (tok0 >= 0) {
                float2 v = make_float2(acc[mi][nj][0] + b0, acc[mi][nj][1] + b1);
                *reinterpret_cast<float2*>(out + (size_t)tok0 * OUT_F + nStart + col) = v;
            }
            if (tok1 >= 0) {
                float2 v = make_float2(acc[mi][nj][2] + b0, acc[mi][nj][3] + b1);
                *reinterpret_cast<float2*>(out + (size_t)tok1 * OUT_F + nStart + col) = v;
            }
        }
    }
}

// ---------------- launcher ----------------
extern "C" void kernel_launch(void* const* d_in, const int* in_sizes, int n_in,
                              void* d_out, int out_size)
{
    const float* input  = (const float*)d_in[0];
    const void*  i_type = d_in[1];
    const float* weight = (const float*)d_in[2];
    const float* bias   = (const float*)d_in[3];
    float*       out    = (float*)d_out;

    cudaFuncSetAttribute(tcl_gemm_kernel,
                         cudaFuncAttributeMaxDynamicSharedMemorySize, SMEM_TOTAL);

    tcl_zero_kernel<<<1, 32>>>();
    tcl_detect_kernel<<<N_TOK / 2 / 256, 256>>>((const int*)i_type);
    tcl_hist_kernel<<<N_TOK / 256, 256>>>(i_type);
    tcl_prefix_kernel<<<1, 32>>>();
    tcl_scatter_kernel<<<N_TOK / 256, 256>>>(i_type);
    tcl_gemm_kernel<<<dim3(OUT_F / BN, MAX_TILES), NTHREADS, SMEM_TOTAL>>>(input, weight, bias, out);
}